// round 1
// baseline (speedup 1.0000x reference)
#include <cuda_runtime.h>
#include <math.h>

#define T_SEQ  2048
#define NBATCH 2
#define DIM    1024
#define HEADS  8
#define NKEYS  256
#define TOPK   32
#define DHEAD  128

// ---------------- scratch (static device globals; no allocation) ----------------
__device__ float g_q   [(size_t)NBATCH * T_SEQ * 2 * DIM];   // (b, t, 2048)
__device__ float g_dots[(size_t)32 * T_SEQ * NKEYS];         // (z = b*16+h*2+p, t, n)
__device__ float g_s1s [(size_t)32 * T_SEQ * TOPK];          // stage-1 scores (sorted desc)
__device__ int   g_s1i [(size_t)32 * T_SEQ * TOPK];          // stage-1 indices
__device__ float g_attn[(size_t)NBATCH * T_SEQ * DIM];       // (b, t, 1024) pre-Wo

// ---------------- generic tiled SGEMM: C = A(MxK) * B(NxK)^T (+bias) ----------------
// BM=BN=128, BK=8, 256 threads, 8x8 per thread. Requires M%128==0, N%128==0, K%8==0.
#define BM 128
#define BN 128
#define BKK 8

__device__ __forceinline__ void sgemm_tile(
    const float* __restrict__ A, const float* __restrict__ B,
    float* __restrict__ C, const float* __restrict__ bias,
    const int K, const int lda, const int ldb, const int ldc)
{
    __shared__ float As[BKK][BM];
    __shared__ float Bs[BKK][BN];

    const int tid  = threadIdx.x;
    const int mblk = blockIdx.y * BM;
    const int nblk = blockIdx.x * BN;

    const int loadRow = tid >> 1;          // 0..127
    const int loadCol = (tid & 1) * 4;     // 0 or 4

    const int tx = tid & 15;               // n sub-tile
    const int ty = tid >> 4;               // m sub-tile

    const float* Ab = A + (size_t)(mblk + loadRow) * lda + loadCol;
    const float* Bb = B + (size_t)(nblk + loadRow) * ldb + loadCol;

    float acc[8][8];
#pragma unroll
    for (int i = 0; i < 8; ++i)
#pragma unroll
        for (int j = 0; j < 8; ++j) acc[i][j] = 0.f;

    for (int k0 = 0; k0 < K; k0 += BKK) {
        float4 a4 = *(const float4*)(Ab + k0);
        float4 b4 = *(const float4*)(Bb + k0);
        As[loadCol + 0][loadRow] = a4.x;
        As[loadCol + 1][loadRow] = a4.y;
        As[loadCol + 2][loadRow] = a4.z;
        As[loadCol + 3][loadRow] = a4.w;
        Bs[loadCol + 0][loadRow] = b4.x;
        Bs[loadCol + 1][loadRow] = b4.y;
        Bs[loadCol + 2][loadRow] = b4.z;
        Bs[loadCol + 3][loadRow] = b4.w;
        __syncthreads();
#pragma unroll
        for (int k = 0; k < BKK; ++k) {
            float ar[8], br[8];
#pragma unroll
            for (int i = 0; i < 8; ++i) ar[i] = As[k][ty * 8 + i];
#pragma unroll
            for (int j = 0; j < 8; ++j) br[j] = Bs[k][tx * 8 + j];
#pragma unroll
            for (int i = 0; i < 8; ++i)
#pragma unroll
                for (int j = 0; j < 8; ++j) acc[i][j] = fmaf(ar[i], br[j], acc[i][j]);
        }
        __syncthreads();
    }

#pragma unroll
    for (int i = 0; i < 8; ++i) {
        float* crow = C + (size_t)(mblk + ty * 8 + i) * ldc + nblk + tx * 8;
        float4 v0, v1;
        if (bias) {
            const float* brow = bias + nblk + tx * 8;
            v0 = make_float4(acc[i][0] + brow[0], acc[i][1] + brow[1],
                             acc[i][2] + brow[2], acc[i][3] + brow[3]);
            v1 = make_float4(acc[i][4] + brow[4], acc[i][5] + brow[5],
                             acc[i][6] + brow[6], acc[i][7] + brow[7]);
        } else {
            v0 = make_float4(acc[i][0], acc[i][1], acc[i][2], acc[i][3]);
            v1 = make_float4(acc[i][4], acc[i][5], acc[i][6], acc[i][7]);
        }
        *(float4*)(crow)     = v0;
        *(float4*)(crow + 4) = v1;
    }
}

// ---------------- kernels ----------------

// q = x @ Wq^T : (4096 x 2048), K=1024
__global__ __launch_bounds__(256) void k_qproj(const float* __restrict__ x,
                                               const float* __restrict__ Wq)
{
    sgemm_tile(x, Wq, g_q, nullptr, DIM, DIM, DIM, 2 * DIM);
}

// dots[z=(b,h,p)][t][n] = q[p,b,t,h,:] . keys[h,n,p,:]  — batched 2048x256, K=128
__global__ __launch_bounds__(256) void k_dots(const float* __restrict__ keys)
{
    const int z = blockIdx.z;
    const int b = z >> 4, h = (z >> 1) & 7, p = z & 1;
    const float* A = g_q + (size_t)b * T_SEQ * (2 * DIM) + p * DIM + h * DHEAD;
    const float* B = keys + ((size_t)h * NKEYS * 2 + p) * DHEAD;  // n-stride = 2*DHEAD
    float* C = g_dots + (size_t)z * T_SEQ * NKEYS;
    sgemm_tile(A, B, C, nullptr, DHEAD, 2 * DIM, 2 * DHEAD, NKEYS);
}

// stage-1 top-32 of 256 per row; one warp per row; outputs sorted descending.
__global__ __launch_bounds__(256) void k_topk1()
{
    const int warp = threadIdx.x >> 5;
    const int lane = threadIdx.x & 31;
    const size_t row = (size_t)blockIdx.x * 8 + warp;
    const float* d = g_dots + row * NKEYS;
    const float NEGINF = __int_as_float(0xff800000);

    float v[8];
#pragma unroll
    for (int j = 0; j < 8; ++j) v[j] = d[j * 32 + lane];

    float* outs = g_s1s + row * TOPK;
    int*   outi = g_s1i + row * TOPK;

    for (int it = 0; it < TOPK; ++it) {
        float bv = NEGINF;
        int   bn = 1 << 30;
#pragma unroll
        for (int j = 0; j < 8; ++j) {
            const int n = j * 32 + lane;
            if (v[j] > bv) { bv = v[j]; bn = n; }
        }
#pragma unroll
        for (int off = 16; off > 0; off >>= 1) {
            const float ov = __shfl_xor_sync(0xffffffffu, bv, off);
            const int   on = __shfl_xor_sync(0xffffffffu, bn, off);
            if (ov > bv || (ov == bv && on < bn)) { bv = ov; bn = on; }
        }
        if (lane == 0) { outs[it] = bv; outi[it] = bn; }
        const int wl = bn & 31, wj = bn >> 5;
#pragma unroll
        for (int j = 0; j < 8; ++j)
            if (lane == wl && j == wj) v[j] = NEGINF;
    }
}

// stage-2: combine sorted halves, Pareto-pruned top-32 of 32x32 sums,
// softmax, gather values, weighted sum. One block per (b, h, t').
__global__ __launch_bounds__(128) void k_stage2(const float* __restrict__ values)
{
    const int tp = blockIdx.x;                 // merged time index t' = 2*i + p
    const int b  = blockIdx.y, h = blockIdx.z;
    const int i  = tp >> 1, p = tp & 1;
    const int z  = ((b * HEADS + h) << 1) + p;
    const size_t baseA = ((size_t)z * T_SEQ + i) * TOPK;                // query time i
    const size_t baseB = ((size_t)z * T_SEQ + (T_SEQ / 2) + i) * TOPK;  // query time th+i

    __shared__ float sA[32], sB[32], csum[128], topS[32], w[32];
    __shared__ int   iA[32], iB[32], topI[32];

    const int tid = threadIdx.x;
    const float NEGINF = __int_as_float(0xff800000);

    if (tid < 32)      { sA[tid] = g_s1s[baseA + tid]; iA[tid] = g_s1i[baseA + tid]; }
    else if (tid < 64) { const int r = tid - 32; sB[r] = g_s1s[baseB + r]; iB[r] = g_s1i[baseB + r]; }
    csum[tid] = NEGINF;
    __syncthreads();

    // Pareto candidate set {(a,c): (a+1)*(c+1) <= 32} has 119 members,
    // enumerated lexicographically (matches flattened a*32+c order for tie-break).
    int a = 0, c = 0;
    float myv = NEGINF;
    if (tid < 119) {
        int base = 0;
        while (base + 32 / (a + 1) <= tid) { base += 32 / (a + 1); ++a; }
        c = tid - base;
        myv = sA[a] + sB[c];
        csum[tid] = myv;
    }
    __syncthreads();

    if (tid < 119) {
        int rank = 0;
        for (int j = 0; j < 119; ++j) {
            const float vj = csum[j];
            rank += (vj > myv) || (vj == myv && j < tid);
        }
        if (rank < 32) {
            topS[rank] = myv;
            topI[rank] = iA[a] * NKEYS + iB[c];
        }
    }
    __syncthreads();

    if (tid < 32) {  // warp 0: softmax over 32 sorted scores (topS[0] = max)
        const float e = expf(topS[tid] - topS[0]);
        float s = e;
#pragma unroll
        for (int off = 16; off > 0; off >>= 1) s += __shfl_xor_sync(0xffffffffu, s, off);
        w[tid] = e / s;
    }
    __syncthreads();

    const float* V = values + (size_t)h * (NKEYS * NKEYS) * DHEAD;
    float acc = 0.f;
#pragma unroll
    for (int j = 0; j < 32; ++j)
        acc = fmaf(w[j], V[(size_t)topI[j] * DHEAD + tid], acc);

    g_attn[((size_t)(b * T_SEQ + tp)) * DIM + h * DHEAD + tid] = acc;
}

// out = attn @ Wo^T + bo : (4096 x 1024), K=1024
__global__ __launch_bounds__(256) void k_outproj(const float* __restrict__ Wo,
                                                 const float* __restrict__ bo,
                                                 float* __restrict__ out)
{
    sgemm_tile(g_attn, Wo, out, bo, DIM, DIM, DIM, DIM);
}

// ---------------- launch ----------------
extern "C" void kernel_launch(void* const* d_in, const int* in_sizes, int n_in,
                              void* d_out, int out_size)
{
    const float* x      = (const float*)d_in[0];
    const float* Wq     = (const float*)d_in[1];
    const float* keys   = (const float*)d_in[2];
    const float* values = (const float*)d_in[3];
    const float* Wo     = (const float*)d_in[4];
    const float* bo     = (const float*)d_in[5];
    float* out = (float*)d_out;

    k_qproj  <<<dim3((2 * DIM) / BN, (NBATCH * T_SEQ) / BM), 256>>>(x, Wq);
    k_dots   <<<dim3(NKEYS / BN, T_SEQ / BM, 32), 256>>>(keys);
    k_topk1  <<<(32 * T_SEQ) / 8, 256>>>();
    k_stage2 <<<dim3(T_SEQ, NBATCH, HEADS), 128>>>(values);
    k_outproj<<<dim3(DIM / BN, (NBATCH * T_SEQ) / BM), 256>>>(Wo, bo, out);
}

// round 7
// speedup vs baseline: 1.5437x; 1.5437x over previous
#include <cuda_runtime.h>
#include <stdint.h>
#include <math.h>

#define T_SEQ  2048
#define NBATCH 2
#define DIM    1024
#define HEADS  8
#define NKEYS  256
#define TOPK   32
#define DHEAD  128

// bf16 stored as raw uint16 — no cuda_bf16.h anywhere.
typedef unsigned short u16;

__device__ __forceinline__ u16 f2b(float v) {
    const uint32_t u = __float_as_uint(v);
    return (u16)((u + 0x7fffu + ((u >> 16) & 1u)) >> 16);   // round-nearest-even
}
__device__ __forceinline__ float b2f(u16 h) {
    return __uint_as_float(((uint32_t)h) << 16);
}

// ---------------- scratch (static device globals; no allocation) ----------------
__device__ __align__(16) u16 g_xhi [(size_t)NBATCH * T_SEQ * DIM];
__device__ __align__(16) u16 g_xlo [(size_t)NBATCH * T_SEQ * DIM];
__device__ __align__(16) u16 g_wqhi[(size_t)2 * DIM * DIM];
__device__ __align__(16) u16 g_wqlo[(size_t)2 * DIM * DIM];
__device__ __align__(16) u16 g_wohi[(size_t)DIM * DIM];
__device__ __align__(16) u16 g_wolo[(size_t)DIM * DIM];
__device__ __align__(16) u16 g_khi [(size_t)16 * NKEYS * DHEAD];   // [zk=h*2+p][n][d]
__device__ __align__(16) u16 g_klo [(size_t)16 * NKEYS * DHEAD];
__device__ __align__(16) u16 g_qhi [(size_t)NBATCH * T_SEQ * 2 * DIM];
__device__ __align__(16) u16 g_qlo [(size_t)NBATCH * T_SEQ * 2 * DIM];
__device__ __align__(16) u16 g_ahi [(size_t)NBATCH * T_SEQ * DIM];  // attn pre-Wo
__device__ __align__(16) u16 g_alo [(size_t)NBATCH * T_SEQ * DIM];
__device__ float g_dots[(size_t)32 * T_SEQ * NKEYS];   // (z = b*16+h*2+p, t, n)
__device__ float g_s1s [(size_t)32 * T_SEQ * TOPK];
__device__ int   g_s1i [(size_t)32 * T_SEQ * TOPK];

// ---------------- tensor-core primitive ----------------
__device__ __forceinline__ void mma16(float* c, const uint32_t* a, const uint32_t* b) {
    asm volatile("mma.sync.aligned.m16n8k16.row.col.f32.bf16.bf16.f32 "
        "{%0,%1,%2,%3},{%4,%5,%6,%7},{%8,%9},{%0,%1,%2,%3};"
        : "+f"(c[0]), "+f"(c[1]), "+f"(c[2]), "+f"(c[3])
        : "r"(a[0]), "r"(a[1]), "r"(a[2]), "r"(a[3]), "r"(b[0]), "r"(b[1]));
}

// ---------------- bf16x3 split GEMM: C = A(MxK) * B(NxK)^T ----------------
// Block tile 128x128, BK=32, 256 threads (8 warps as 4m x 2n, warp tile 32x64).
// Fragments via per-thread LDS using the mma.m16n8k16 fragment spec directly.
#define PAD 40

template<bool SPLIT_OUT, bool BIAS>
__device__ __forceinline__ void gemm3(
    const u16* __restrict__ Ahi, const u16* __restrict__ Alo,
    const u16* __restrict__ Bhi, const u16* __restrict__ Blo,
    const int K, const int lda, const int ldb, const int ldc,
    float* __restrict__ C, u16* __restrict__ Chi, u16* __restrict__ Clo,
    const float* __restrict__ bias, const int m0, const int n0)
{
    __shared__ u16 sm[4 * 128 * PAD];

    const int tid  = threadIdx.x;
    const int lane = tid & 31, warp = tid >> 5;
    const int wm = warp >> 1, wn = warp & 1;
    const int qr = lane >> 2;           // 0..7   fragment row
    const int qc = (lane & 3) * 2;      // 0,2,4,6 fragment k pair

    // gmem -> smem: each thread moves one uint4 (8 u16) x2 rows per matrix
    const int lrow = tid >> 2;          // 0..63
    const int lcol = (tid & 3) * 8;     // u16 elems

    const u16* gAh = Ahi + (size_t)(m0 + lrow) * lda + lcol;
    const u16* gAl = Alo + (size_t)(m0 + lrow) * lda + lcol;
    const u16* gBh = Bhi + (size_t)(n0 + lrow) * ldb + lcol;
    const u16* gBl = Blo + (size_t)(n0 + lrow) * ldb + lcol;
    const size_t skA = (size_t)64 * lda, skB = (size_t)64 * ldb;

    const int MOFF = 128 * PAD * 2;     // bytes per matrix buffer
    const int HOFF = 64 * PAD * 2;
    char* swp = (char*)sm + ((size_t)lrow * PAD + lcol) * 2;
    const char* smc = (const char*)sm;

#define AHI_F(r, k) (*(const uint32_t*)(smc            + (((r) * PAD + (k)) * 2)))
#define ALO_F(r, k) (*(const uint32_t*)(smc +     MOFF + (((r) * PAD + (k)) * 2)))
#define BHI_F(r, k) (*(const uint32_t*)(smc + 2 * MOFF + (((r) * PAD + (k)) * 2)))
#define BLO_F(r, k) (*(const uint32_t*)(smc + 3 * MOFF + (((r) * PAD + (k)) * 2)))

    float c[2][8][4];
#pragma unroll
    for (int i = 0; i < 2; ++i)
#pragma unroll
        for (int j = 0; j < 8; ++j)
#pragma unroll
            for (int q = 0; q < 4; ++q) c[i][j][q] = 0.f;

    for (int k0 = 0; k0 < K; k0 += 32) {
        const uint4 vah0 = *(const uint4*)(gAh + k0);
        const uint4 vah1 = *(const uint4*)(gAh + k0 + skA);
        const uint4 val0 = *(const uint4*)(gAl + k0);
        const uint4 val1 = *(const uint4*)(gAl + k0 + skA);
        const uint4 vbh0 = *(const uint4*)(gBh + k0);
        const uint4 vbh1 = *(const uint4*)(gBh + k0 + skB);
        const uint4 vbl0 = *(const uint4*)(gBl + k0);
        const uint4 vbl1 = *(const uint4*)(gBl + k0 + skB);
        __syncthreads();                      // previous iter's compute done
        *(uint4*)(swp)                    = vah0;
        *(uint4*)(swp + HOFF)             = vah1;
        *(uint4*)(swp + MOFF)             = val0;
        *(uint4*)(swp + MOFF + HOFF)      = val1;
        *(uint4*)(swp + 2 * MOFF)         = vbh0;
        *(uint4*)(swp + 2 * MOFF + HOFF)  = vbh1;
        *(uint4*)(swp + 3 * MOFF)         = vbl0;
        *(uint4*)(swp + 3 * MOFF + HOFF)  = vbl1;
        __syncthreads();                      // tiles visible

#pragma unroll
        for (int ks = 0; ks < 2; ++ks) {
            const int kk = ks * 16 + qc;      // this thread's k pair base

            uint32_t ah[2][4], al[2][4], bh[8][2], bl[8][2];
#pragma unroll
            for (int tm = 0; tm < 2; ++tm) {
                const int r = wm * 32 + tm * 16 + qr;
                ah[tm][0] = AHI_F(r,     kk);
                ah[tm][1] = AHI_F(r + 8, kk);
                ah[tm][2] = AHI_F(r,     kk + 8);
                ah[tm][3] = AHI_F(r + 8, kk + 8);
                al[tm][0] = ALO_F(r,     kk);
                al[tm][1] = ALO_F(r + 8, kk);
                al[tm][2] = ALO_F(r,     kk + 8);
                al[tm][3] = ALO_F(r + 8, kk + 8);
            }
#pragma unroll
            for (int tn = 0; tn < 8; ++tn) {
                const int r = wn * 64 + tn * 8 + qr;
                bh[tn][0] = BHI_F(r, kk);
                bh[tn][1] = BHI_F(r, kk + 8);
                bl[tn][0] = BLO_F(r, kk);
                bl[tn][1] = BLO_F(r, kk + 8);
            }
            // P1: Ahi*Bhi   P2: Ahi*Blo   P3: Alo*Bhi
#pragma unroll
            for (int tm = 0; tm < 2; ++tm)
#pragma unroll
                for (int tn = 0; tn < 8; ++tn) mma16(c[tm][tn], ah[tm], bh[tn]);
#pragma unroll
            for (int tm = 0; tm < 2; ++tm)
#pragma unroll
                for (int tn = 0; tn < 8; ++tn) mma16(c[tm][tn], ah[tm], bl[tn]);
#pragma unroll
            for (int tm = 0; tm < 2; ++tm)
#pragma unroll
                for (int tn = 0; tn < 8; ++tn) mma16(c[tm][tn], al[tm], bh[tn]);
        }
    }
#undef AHI_F
#undef ALO_F
#undef BHI_F
#undef BLO_F

    // epilogue (c fragment: c0,c1 = row qr cols qc..+1; c2,c3 = row qr+8)
    const int r0 = qr, cc = qc;
#pragma unroll
    for (int tm = 0; tm < 2; ++tm)
#pragma unroll
        for (int tn = 0; tn < 8; ++tn) {
            const int row = m0 + wm * 32 + tm * 16 + r0;
            const int col = n0 + wn * 64 + tn * 8 + cc;
#pragma unroll
            for (int hr = 0; hr < 2; ++hr) {
                const int rr = row + hr * 8;
                float v0 = c[tm][tn][hr * 2 + 0];
                float v1 = c[tm][tn][hr * 2 + 1];
                if (BIAS) { v0 += bias[col]; v1 += bias[col + 1]; }
                if (SPLIT_OUT) {
                    const u16 h0 = f2b(v0), h1 = f2b(v1);
                    const u16 l0 = f2b(v0 - b2f(h0)), l1 = f2b(v1 - b2f(h1));
                    *(uint32_t*)(Chi + (size_t)rr * ldc + col) =
                        ((uint32_t)h1 << 16) | (uint32_t)h0;
                    *(uint32_t*)(Clo + (size_t)rr * ldc + col) =
                        ((uint32_t)l1 << 16) | (uint32_t)l0;
                } else {
                    float2 v; v.x = v0; v.y = v1;
                    *(float2*)(C + (size_t)rr * ldc + col) = v;
                }
            }
        }
}

// ---------------- GEMM entry kernels (globals referenced in DEVICE code only) ----
__global__ __launch_bounds__(256) void k_qproj_t() {
    gemm3<true, false>(g_xhi, g_xlo, g_wqhi, g_wqlo,
                       DIM, DIM, DIM, 2 * DIM,
                       (float*)0, g_qhi, g_qlo, (const float*)0,
                       blockIdx.y * 128, blockIdx.x * 128);
}

__global__ __launch_bounds__(256) void k_dots_t() {
    const int z = blockIdx.z;
    const int b = z >> 4, h = (z >> 1) & 7, p = z & 1;
    const size_t aoff = (size_t)b * T_SEQ * (2 * DIM) + p * DIM + h * DHEAD;
    const size_t boff = (size_t)((h << 1) | p) * NKEYS * DHEAD;
    gemm3<false, false>(g_qhi + aoff, g_qlo + aoff, g_khi + boff, g_klo + boff,
                        DHEAD, 2 * DIM, DHEAD, NKEYS,
                        g_dots + (size_t)z * T_SEQ * NKEYS, (u16*)0, (u16*)0,
                        (const float*)0,
                        blockIdx.y * 128, blockIdx.x * 128);
}

__global__ __launch_bounds__(256) void k_outproj_t(const float* __restrict__ bo,
                                                   float* __restrict__ out) {
    gemm3<false, true>(g_ahi, g_alo, g_wohi, g_wolo,
                       DIM, DIM, DIM, DIM,
                       out, (u16*)0, (u16*)0, bo,
                       blockIdx.y * 128, blockIdx.x * 128);
}

// ---------------- split conversions ----------------
// CRITICAL: destination __device__ globals must be named in DEVICE code, never
// passed as host-side kernel arguments (host sees shadow addresses; on GB300
// ATS silently writes host memory and the device copies stay zero).
__device__ __forceinline__ void split_one(const float* __restrict__ s,
                                          u16* __restrict__ hi,
                                          u16* __restrict__ lo, int n) {
    const int i = blockIdx.x * 256 + threadIdx.x;
    if (i < n) {
        const float v = s[i];
        const u16 a = f2b(v);
        hi[i] = a;
        lo[i] = f2b(v - b2f(a));
    }
}
__global__ void k_split_x (const float* __restrict__ s) { split_one(s, g_xhi,  g_xlo,  NBATCH * T_SEQ * DIM); }
__global__ void k_split_wq(const float* __restrict__ s) { split_one(s, g_wqhi, g_wqlo, 2 * DIM * DIM); }
__global__ void k_split_wo(const float* __restrict__ s) { split_one(s, g_wohi, g_wolo, DIM * DIM); }

// keys[h][n][p][d] -> g_khi/klo[(h*2+p)][n][d]
__global__ void k_split_keys(const float* __restrict__ keys) {
    const int i = blockIdx.x * 256 + threadIdx.x;
    if (i < 16 * NKEYS * DHEAD) {
        const int d = i & 127;
        const int n = (i >> 7) & 255;
        const int zk = i >> 15;
        const int h = zk >> 1, p = zk & 1;
        const float v = keys[(((size_t)(h * NKEYS + n) * 2 + p) << 7) + d];
        const u16 a = f2b(v);
        g_khi[i] = a;
        g_klo[i] = f2b(v - b2f(a));
    }
}

// ---------------- stage-1 top-32 of 256 per row (one warp/row) ----------------
__global__ __launch_bounds__(256) void k_topk1() {
    const int warp = threadIdx.x >> 5;
    const int lane = threadIdx.x & 31;
    const size_t row = (size_t)blockIdx.x * 8 + warp;
    const float* d = g_dots + row * NKEYS;
    const float NEGINF = __int_as_float(0xff800000);

    float v[8];
#pragma unroll
    for (int j = 0; j < 8; ++j) v[j] = d[j * 32 + lane];

    float* outs = g_s1s + row * TOPK;
    int*   outi = g_s1i + row * TOPK;

    for (int it = 0; it < TOPK; ++it) {
        float bv = NEGINF;
        int   bn = 1 << 30;
#pragma unroll
        for (int j = 0; j < 8; ++j) {
            const int n = j * 32 + lane;
            if (v[j] > bv) { bv = v[j]; bn = n; }
        }
#pragma unroll
        for (int off = 16; off > 0; off >>= 1) {
            const float ov = __shfl_xor_sync(0xffffffffu, bv, off);
            const int   on = __shfl_xor_sync(0xffffffffu, bn, off);
            if (ov > bv || (ov == bv && on < bn)) { bv = ov; bn = on; }
        }
        if (lane == 0) { outs[it] = bv; outi[it] = bn; }
        const int wl = bn & 31, wj = bn >> 5;
#pragma unroll
        for (int j = 0; j < 8; ++j)
            if (lane == wl && j == wj) v[j] = NEGINF;
    }
}

// ---------------- stage-2: combine + softmax + gather (writes split attn) ----------------
__global__ __launch_bounds__(128) void k_stage2(const float* __restrict__ values) {
    const int tp = blockIdx.x;
    const int b  = blockIdx.y, h = blockIdx.z;
    const int i  = tp >> 1, p = tp & 1;
    const int z  = ((b * HEADS + h) << 1) + p;
    const size_t baseA = ((size_t)z * T_SEQ + i) * TOPK;
    const size_t baseB = ((size_t)z * T_SEQ + (T_SEQ / 2) + i) * TOPK;

    __shared__ float sA[32], sB[32], csum[128], topS[32], w[32];
    __shared__ int   iA[32], iB[32], topI[32];

    const int tid = threadIdx.x;
    const float NEGINF = __int_as_float(0xff800000);

    if (tid < 32)      { sA[tid] = g_s1s[baseA + tid]; iA[tid] = g_s1i[baseA + tid]; }
    else if (tid < 64) { const int r = tid - 32; sB[r] = g_s1s[baseB + r]; iB[r] = g_s1i[baseB + r]; }
    csum[tid] = NEGINF;
    __syncthreads();

    // Pareto candidate set {(a,c): (a+1)*(c+1) <= 32}, 119 members.
    int a = 0, c = 0;
    float myv = NEGINF;
    if (tid < 119) {
        int base = 0;
        while (base + 32 / (a + 1) <= tid) { base += 32 / (a + 1); ++a; }
        c = tid - base;
        myv = sA[a] + sB[c];
        csum[tid] = myv;
    }
    __syncthreads();

    if (tid < 119) {
        int rank = 0;
        for (int j = 0; j < 119; ++j) {
            const float vj = csum[j];
            rank += (vj > myv) || (vj == myv && j < tid);
        }
        if (rank < 32) {
            topS[rank] = myv;
            topI[rank] = iA[a] * NKEYS + iB[c];
        }
    }
    __syncthreads();

    if (tid < 32) {
        const float e = expf(topS[tid] - topS[0]);
        float s = e;
#pragma unroll
        for (int off = 16; off > 0; off >>= 1) s += __shfl_xor_sync(0xffffffffu, s, off);
        w[tid] = e / s;
    }
    __syncthreads();

    const float* V = values + (size_t)h * (NKEYS * NKEYS) * DHEAD;
    float acc = 0.f;
#pragma unroll
    for (int j = 0; j < 32; ++j)
        acc = fmaf(w[j], V[(size_t)topI[j] * DHEAD + tid], acc);

    const size_t oidx = ((size_t)(b * T_SEQ + tp)) * DIM + h * DHEAD + tid;
    const u16 hv = f2b(acc);
    g_ahi[oidx] = hv;
    g_alo[oidx] = f2b(acc - b2f(hv));
}

// ---------------- launch ----------------
extern "C" void kernel_launch(void* const* d_in, const int* in_sizes, int n_in,
                              void* d_out, int out_size)
{
    const float* x      = (const float*)d_in[0];
    const float* Wq     = (const float*)d_in[1];
    const float* keys   = (const float*)d_in[2];
    const float* values = (const float*)d_in[3];
    const float* Wo     = (const float*)d_in[4];
    const float* bo     = (const float*)d_in[5];
    float* out = (float*)d_out;

    const int nX  = NBATCH * T_SEQ * DIM;
    const int nWq = 2 * DIM * DIM;
    const int nWo = DIM * DIM;

    k_split_x <<<(nX  + 255) / 256, 256>>>(x);
    k_split_wq<<<(nWq + 255) / 256, 256>>>(Wq);
    k_split_wo<<<(nWo + 255) / 256, 256>>>(Wo);
    k_split_keys<<<(16 * NKEYS * DHEAD) / 256, 256>>>(keys);

    k_qproj_t<<<dim3(16, 32), 256>>>();
    k_dots_t <<<dim3(2, 16, 32), 256>>>();
    k_topk1  <<<(32 * T_SEQ) / 8, 256>>>();
    k_stage2 <<<dim3(T_SEQ, NBATCH, HEADS), 128>>>(values);
    k_outproj_t<<<dim3(8, 32), 256>>>(bo, out);
}